// round 4
// baseline (speedup 1.0000x reference)
#include <cuda_runtime.h>

// SeparateLoss: mean over the N x N cosine-sim matrix masked by label
// inequality. Binary labels => (2/N^2) * dot(S0, S1),
// Sk = sum of L2-normalized feature rows with label k.
//
// feat [4, 64, 128, 128] f32, label [4, 1, 128, 128] i32.
// Nearest 128->64 picks even indices. N = 16384, C = 64.
//
// One balanced wave: 128 blocks (<=1 per SM), each handles 2 output rows.
// Each thread front-batches 16 float4 loads into registers (max MLP), then
// transposes to smem. Last block (int ticket) reduces deterministically.

#define B 4
#define C 64
#define H 128
#define W 128
#define X 64                        // output spatial size
#define NROW (B * X)                // 256 output rows total
#define NBLK 128                    // blocks: 2 rows each
#define NSLOT (2 * C)               // (class, channel) slots
#define NTOT 16384.0f
#define LDS_PITCH 65                // padded row stride in smem

__device__ __align__(16) float g_partial[NSLOT * NROW];  // [slot][row], fully rewritten
__device__ int g_ticket = 0;

__global__ void __launch_bounds__(256) separate_fused(
    const float* __restrict__ feat, const int* __restrict__ label,
    float* __restrict__ out)
{
    // [row(2)][ch(64)][xi(64 padded to 65)]
    __shared__ float sm[2 * C * LDS_PITCH];
    __shared__ float invn[2 * X];
    __shared__ int   lab[2 * X];
    __shared__ float S[NSLOT];
    __shared__ int   is_last;

    const int b   = blockIdx.y;        // 0..3
    const int bx  = blockIdx.x;        // 0..31
    const int tid = threadIdx.x;

    // ---- Load: 4096 float4 chunks (2 rows x 64ch x 32), 16 per thread ----
    // chunk g: r = g>>11, ch = (g>>5)&63, xj = g&31 ; y = 4*bx + 2*r
    float4 v[16];
    #pragma unroll
    for (int k = 0; k < 16; k++) {
        const int g  = tid + k * 256;
        const int r  = g >> 11;
        const int ch = (g >> 5) & 63;
        const int xj = g & 31;
        const int y  = 4 * bx + 2 * r;
        v[k] = reinterpret_cast<const float4*>(
                   feat + (((size_t)b * C + ch) * H + y) * W)[xj];
    }
    if (tid < 2 * X) {
        const int r  = tid >> 6;
        const int xi = tid & 63;
        lab[tid] = label[b * (H * W) + (4 * bx + 2 * r) * W + 2 * xi];
    }
    #pragma unroll
    for (int k = 0; k < 16; k++) {
        const int g  = tid + k * 256;
        const int r  = g >> 11;
        const int ch = (g >> 5) & 63;
        const int xj = g & 31;
        float* d = sm + (r * C + ch) * LDS_PITCH + 2 * xj;
        d[0] = v[k].x;                 // even x
        d[1] = v[k].z;
    }
    __syncthreads();

    // ---- Inverse norms: 2 lanes per position, 32 channels each ----
    {
        const int p    = tid >> 1;     // 0..127 : row*64 + xi
        const int half = tid & 1;
        const int r    = p >> 6;
        const int xi   = p & 63;
        const float* base = sm + (r * C) * LDS_PITCH + xi;
        float s = 0.f;
        #pragma unroll
        for (int k = 0; k < 32; k++) {
            const float f = base[(2 * k + half) * LDS_PITCH];
            s += f * f;
        }
        s += __shfl_xor_sync(0xffffffffu, s, 1);
        if (half == 0) invn[p] = 1.0f / fmaxf(sqrtf(s), 1e-12f);
    }
    __syncthreads();

    // ---- Class sums: 2 lanes per (row, channel), 32 positions each ----
    {
        const int rc  = tid >> 1;      // row*64 + ch
        const int sub = tid & 1;
        const int r   = rc >> 6;
        const int ch  = rc & 63;
        const float* base = sm + (r * C + ch) * LDS_PITCH + sub * 32;
        const float* nv   = invn + r * X + sub * 32;
        const int*   lv   = lab  + r * X + sub * 32;
        float s0 = 0.f, s1 = 0.f;
        #pragma unroll
        for (int k = 0; k < 32; k++) {
            const float f = base[k] * nv[k];
            if (lv[k] == 0) s0 += f; else s1 += f;
        }
        s0 += __shfl_xor_sync(0xffffffffu, s0, 1);
        s1 += __shfl_xor_sync(0xffffffffu, s1, 1);
        if (sub == 0) {
            const int row = b * X + 2 * bx + r;       // global output row 0..255
            g_partial[ch * NROW + row]       = s0;    // class 0
            g_partial[(C + ch) * NROW + row] = s1;    // class 1
        }
    }

    // ---- Last-block ticket ----
    __threadfence();
    if (tid == 0) {
        const int t = atomicAdd(&g_ticket, 1);
        is_last = (t == NBLK - 1);
    }
    __syncthreads();
    if (!is_last) return;
    __threadfence();                   // acquire: make all partials visible

    // ---- Deterministic final reduction ----
    {
        const int slot = tid >> 1;     // 0..127
        const int part = tid & 1;
        const float4* p =
            reinterpret_cast<const float4*>(g_partial + slot * NROW) + part * 32;
        float s = 0.f;
        #pragma unroll
        for (int i = 0; i < 32; i++) {
            const float4 w = p[i];
            s += (w.x + w.y) + (w.z + w.w);
        }
        s += __shfl_xor_sync(0xffffffffu, s, 1);
        if (part == 0) S[slot] = s;
    }
    __syncthreads();

    if (tid < 32) {
        float d = S[tid] * S[C + tid] + S[tid + 32] * S[C + tid + 32];
        #pragma unroll
        for (int o = 16; o > 0; o >>= 1)
            d += __shfl_down_sync(0xffffffffu, d, o);
        if (tid == 0) {
            out[0] = d * (2.0f / (NTOT * NTOT));
            g_ticket = 0;              // rearm for next graph replay
        }
    }
}

extern "C" void kernel_launch(void* const* d_in, const int* in_sizes, int n_in,
                              void* d_out, int out_size)
{
    const float* feat  = (const float*)d_in[0];
    const int*   label = (const int*)d_in[1];
    float*       out   = (float*)d_out;

    (void)in_sizes; (void)n_in; (void)out_size;

    separate_fused<<<dim3(32, B), 256>>>(feat, label, out);
}

// round 5
// speedup vs baseline: 1.1320x; 1.1320x over previous
#include <cuda_runtime.h>

// SeparateLoss: mean over the N x N cosine-sim matrix masked by label
// inequality. Binary labels => (2/N^2) * dot(S0, S1),
// Sk = sum of L2-normalized feature rows with label k.
//
// feat [4, 64, 128, 128] f32, label [4, 1, 128, 128] i32.
// Nearest 128->64 picks even indices. N = 16384, C = 64.
//
// 256 blocks x 256 threads; block = one output row (64 positions).
// Warp (cg, ph) loads 16 channels x 32 positions straight into registers
// (16 independent scalar LDGs, front-batched -> MLP 16/thread). Feat is
// read exactly once. All smem phases are bank-conflict-free.
// Last block (int ticket) reduces all partials in fixed order.

#define B 4
#define C 64
#define H 128
#define W 128
#define X 64
#define NBLK 256                    // one block per output row
#define NSLOT 128                   // (class, channel)
#define NTOT 16384.0f

__device__ __align__(16) float g_partial[NSLOT * NBLK];  // [slot][blk], fully rewritten
__device__ int g_ticket = 0;

__global__ void __launch_bounds__(256) separate_fused(
    const float* __restrict__ feat, const int* __restrict__ label,
    float* __restrict__ out)
{
    __shared__ float sq[4 * X];        // [cg][pos] partial sumsq
    __shared__ float T[C * 65];        // [ch][pos], pitch 65 (conflict-free)
    __shared__ int   lab[X];
    __shared__ float G[2 * C * 5];     // [class][ch][q], pitch 5 (conflict-free)
    __shared__ float S[NSLOT];
    __shared__ int   is_last;

    const int bx   = blockIdx.x;       // 0..255
    const int b    = bx >> 6;
    const int yi   = bx & 63;
    const int tid  = threadIdx.x;
    const int w    = tid >> 5;
    const int lane = tid & 31;
    const int cg   = w & 3;            // channel group: ch in [cg*16, cg*16+16)
    const int ph   = w >> 2;           // position half
    const int cset = cg * 16;
    const int pos  = ph * 32 + lane;   // 0..63

    // ---- 16 independent scalar loads into registers (front-batched) ----
    const float* base =
        feat + (((size_t)(b * C + cset) * H) + 2 * yi) * W + 2 * pos;
    float v[16];
    #pragma unroll
    for (int k = 0; k < 16; k++)
        v[k] = base[(size_t)k * (H * W)];

    if (tid < X)
        lab[tid] = label[b * (H * W) + 2 * yi * W + 2 * tid];

    // ---- per-lane sumsq over 16 channels, cross-warp combine via smem ----
    float s = 0.f;
    #pragma unroll
    for (int k = 0; k < 16; k++)
        s += v[k] * v[k];
    sq[cg * X + pos] = s;              // each (cg,pos) written exactly once
    __syncthreads();

    const float nsq  = ((sq[pos] + sq[X + pos]) + (sq[2 * X + pos] + sq[3 * X + pos]));
    const float invn = 1.0f / fmaxf(sqrtf(nsq), 1e-12f);

    // ---- write normalized values transposed: T[ch][pos] ----
    #pragma unroll
    for (int k = 0; k < 16; k++)
        T[(cset + k) * 65 + pos] = v[k] * invn;
    __syncthreads();

    // ---- class sums: thread (q, ch) sums 16 positions for its channel ----
    {
        const int ch = tid & 63;       // warp = 32 consecutive ch -> conflict-free
        const int q  = tid >> 6;       // position quarter
        float s0 = 0.f, s1 = 0.f;
        #pragma unroll
        for (int j = 0; j < 16; j++) {
            const int   p = q * 16 + j;
            const float t = T[ch * 65 + p];
            if (lab[p] == 0) s0 += t; else s1 += t;   // lab[p]: broadcast
        }
        G[ch * 5 + q]           = s0;  // pitch 5: 5*ch+q distinct mod 32
        G[5 * C + ch * 5 + q]   = s1;
    }
    __syncthreads();

    if (tid < 128) {
        const int cls = tid >> 6;
        const int ch  = tid & 63;
        const float* g = G + cls * (5 * C) + ch * 5;
        const float sum = ((g[0] + g[1]) + (g[2] + g[3]));   // fixed order
        g_partial[(cls * C + ch) * NBLK + bx] = sum;
    }

    // ---- last-block ticket ----
    __threadfence();
    if (tid == 0) {
        const int t = atomicAdd(&g_ticket, 1);
        is_last = (t == NBLK - 1);
    }
    __syncthreads();
    if (!is_last) return;
    __threadfence();                   // acquire all partials

    // ---- deterministic final reduction: 2 threads per slot, 32 float4 ----
    {
        const int slot = tid >> 1;
        const int part = tid & 1;
        const float4* p =
            reinterpret_cast<const float4*>(g_partial + slot * NBLK) + part * 32;
        float acc = 0.f;
        #pragma unroll
        for (int i = 0; i < 32; i++) {
            const float4 u = p[i];
            acc += (u.x + u.y) + (u.z + u.w);
        }
        acc += __shfl_xor_sync(0xffffffffu, acc, 1);
        if (part == 0) S[slot] = acc;
    }
    __syncthreads();

    if (tid < 32) {
        float d = S[tid] * S[C + tid] + S[tid + 32] * S[C + tid + 32];
        #pragma unroll
        for (int o = 16; o > 0; o >>= 1)
            d += __shfl_down_sync(0xffffffffu, d, o);
        if (tid == 0) {
            out[0] = d * (2.0f / (NTOT * NTOT));
            g_ticket = 0;              // rearm for next replay
        }
    }
}

extern "C" void kernel_launch(void* const* d_in, const int* in_sizes, int n_in,
                              void* d_out, int out_size)
{
    const float* feat  = (const float*)d_in[0];
    const int*   label = (const int*)d_in[1];
    float*       out   = (float*)d_out;

    (void)in_sizes; (void)n_in; (void)out_size;

    separate_fused<<<NBLK, 256>>>(feat, label, out);
}

// round 6
// speedup vs baseline: 1.1575x; 1.0225x over previous
#include <cuda_runtime.h>

// SeparateLoss: mean over the N x N cosine-sim matrix masked by label
// inequality. Binary labels => (2/N^2) * dot(S0, S1),
// Sk = sum of L2-normalized feature rows with label k.
//
// feat [4, 64, 128, 128] f32, label [4, 1, 128, 128] i32.
// Nearest 128->64 picks even indices. N = 16384, C = 64.
//
// 256 blocks x 256 threads; block = one output row.
// Per thread: 8 x LDG.128 (front-batched), sumsq folded in registers,
// float2 smem transpose. Last block (int ticket) reduces in fixed order.

#define B 4
#define C 64
#define H 128
#define W 128
#define X 64
#define NBLK 256
#define NSLOT 128
#define NTOT 16384.0f
#define TP 66                       // T pitch (floats): float2-aligned stores

__device__ __align__(16) float g_partial[NSLOT * NBLK];  // [slot][blk], fully rewritten
__device__ int g_ticket = 0;

__global__ void __launch_bounds__(256) separate_fused(
    const float* __restrict__ feat, const int* __restrict__ label,
    float* __restrict__ out)
{
    __shared__ float T[C * TP];        // [ch][pos] normalized-to-be values (raw first)
    __shared__ float sq[8 * TP];       // [chgrp][pos] sumsq partials
    __shared__ float invn[X];
    __shared__ int   lab[X];
    __shared__ float G[2 * C * 5];     // [class][ch][q], pitch 5
    __shared__ float S[NSLOT];
    __shared__ int   is_last;

    const int bx  = blockIdx.x;        // 0..255 = output row
    const int b   = bx >> 6;
    const int yi  = bx & 63;
    const int tid = threadIdx.x;
    const int g0  = tid >> 5;          // channel-group base 0..7
    const int xj  = tid & 31;          // float4 index: positions 2xj, 2xj+1

    // ---- 8 x LDG.128: channels g0+8k, row y=2*yi, x = 4xj..4xj+3 ----
    const float4* fb = reinterpret_cast<const float4*>(
        feat + (((size_t)(b * C + g0) * H) + 2 * yi) * W) + xj;
    float4 v[8];
    #pragma unroll
    for (int k = 0; k < 8; k++)
        v[k] = fb[(size_t)(8 * k) * (H * W / 4)];

    if (tid < X)
        lab[tid] = label[b * (H * W) + 2 * yi * W + 2 * tid];

    // ---- sumsq partials in registers: 8 channels for 2 positions ----
    {
        float p0 = 0.f, p1 = 0.f;
        #pragma unroll
        for (int k = 0; k < 8; k++) {
            p0 += v[k].x * v[k].x;     // pos 2xj   (x = 4xj)
            p1 += v[k].z * v[k].z;     // pos 2xj+1 (x = 4xj+2)
        }
        *reinterpret_cast<float2*>(&sq[g0 * TP + 2 * xj]) = make_float2(p0, p1);
    }
    // ---- transpose raw values: T[ch][pos], float2 per (ch, posPair) ----
    #pragma unroll
    for (int k = 0; k < 8; k++)
        *reinterpret_cast<float2*>(&T[(g0 + 8 * k) * TP + 2 * xj]) =
            make_float2(v[k].x, v[k].z);
    __syncthreads();

    // ---- inverse norms (fixed-order sum over 8 groups) ----
    if (tid < X) {
        const float a = (sq[0 * TP + tid] + sq[1 * TP + tid]) +
                        (sq[2 * TP + tid] + sq[3 * TP + tid]);
        const float c = (sq[4 * TP + tid] + sq[5 * TP + tid]) +
                        (sq[6 * TP + tid] + sq[7 * TP + tid]);
        invn[tid] = 1.0f / fmaxf(sqrtf(a + c), 1e-12f);
    }
    __syncthreads();

    // ---- class sums: thread (q, ch), 16 positions each ----
    {
        const int ch = tid & 63;
        const int q  = tid >> 6;
        float s0 = 0.f, s1 = 0.f;
        #pragma unroll
        for (int j = 0; j < 16; j++) {
            const int   p = q * 16 + j;
            const float c = T[ch * TP + p] * invn[p];
            if (lab[p] == 0) s0 += c; else s1 += c;
        }
        G[ch * 5 + q]         = s0;
        G[5 * C + ch * 5 + q] = s1;
    }
    __syncthreads();

    if (tid < 128) {
        const int cls = tid >> 6;
        const int ch  = tid & 63;
        const float* g = G + cls * (5 * C) + ch * 5;
        g_partial[(cls * C + ch) * NBLK + bx] = (g[0] + g[1]) + (g[2] + g[3]);
    }

    // ---- last-block ticket ----
    __threadfence();
    if (tid == 0) {
        const int t = atomicAdd(&g_ticket, 1);
        is_last = (t == NBLK - 1);
    }
    __syncthreads();
    if (!is_last) return;
    __threadfence();                   // acquire all partials

    // ---- deterministic final reduction: 2 threads/slot, 32 float4 each ----
    {
        const int slot = tid >> 1;
        const int part = tid & 1;
        const float4* p =
            reinterpret_cast<const float4*>(g_partial + slot * NBLK) + part * 32;
        float acc = 0.f;
        #pragma unroll
        for (int i = 0; i < 32; i++) {
            const float4 u = p[i];
            acc += (u.x + u.y) + (u.z + u.w);
        }
        acc += __shfl_xor_sync(0xffffffffu, acc, 1);
        if (part == 0) S[slot] = acc;
    }
    __syncthreads();

    if (tid < 32) {
        float d = S[tid] * S[C + tid] + S[tid + 32] * S[C + tid + 32];
        #pragma unroll
        for (int o = 16; o > 0; o >>= 1)
            d += __shfl_down_sync(0xffffffffu, d, o);
        if (tid == 0) {
            out[0] = d * (2.0f / (NTOT * NTOT));
            g_ticket = 0;              // rearm for next replay
        }
    }
}

extern "C" void kernel_launch(void* const* d_in, const int* in_sizes, int n_in,
                              void* d_out, int out_size)
{
    const float* feat  = (const float*)d_in[0];
    const int*   label = (const int*)d_in[1];
    float*       out   = (float*)d_out;

    (void)in_sizes; (void)n_in; (void)out_size;

    separate_fused<<<NBLK, 256>>>(feat, label, out);
}